// round 12
// baseline (speedup 1.0000x reference)
#include <cuda_runtime.h>
#include <cstdint>

// loss = max((2/(N*M)) * dot(colsum(a), colsum(b)), 1e-7)
// TMA-path experiment: cp.async.bulk (UBLKCP) double-buffered 8KB chunks
// into smem, reduce from smem. Bypasses the LDG/L1tex path entirely.

#define TPB 128
#define BPM 592                  // CTAs per matrix
#define GRID (2 * BPM)           // 1184
#define CHUNK_BYTES 8192         // 4 rows of 512 floats
#define CHUNK_F4 512
#define CPM 4096                 // chunks per matrix (32MB / 8KB)
// CTA bid takes chunks bid + k*BPM. bid < 544 -> 7 chunks, else 6. (544*7+48*6=4096)

__device__ float g_colsum[1024];   // [0..511]=colsum(a), [512..1023]=colsum(b)
__device__ unsigned g_count;

__device__ __forceinline__ uint32_t s2u(const void* p) {
    return (uint32_t)__cvta_generic_to_shared(p);
}

__global__ void __launch_bounds__(TPB) qgc_tma(
    const float* __restrict__ a, const float* __restrict__ b,
    float* __restrict__ out)
{
    __shared__ __align__(128) float4 s_buf[2][CHUNK_F4];   // 2 x 8KB
    __shared__ __align__(8) unsigned long long s_mbar[2];
    __shared__ unsigned s_rank;
    __shared__ double s_warp[4];

    const int mat = blockIdx.x & 1;
    const int bid = blockIdx.x >> 1;
    const int t   = threadIdx.x;
    const char* __restrict__ src = (const char*)(mat ? b : a);

    const int n_chunks = (bid < (CPM - 6 * BPM)) ? 7 : 6;

    const uint32_t mb[2] = { s2u(&s_mbar[0]), s2u(&s_mbar[1]) };
    const uint32_t sb[2] = { s2u(&s_buf[0][0]), s2u(&s_buf[1][0]) };

    if (t == 0) {
        asm volatile("mbarrier.init.shared.b64 [%0], 1;" :: "r"(mb[0]) : "memory");
        asm volatile("mbarrier.init.shared.b64 [%0], 1;" :: "r"(mb[1]) : "memory");
        asm volatile("fence.proxy.async.shared::cta;" ::: "memory");
    }
    __syncthreads();

    // prologue: issue chunks 0 and 1
    if (t == 0) {
        #pragma unroll
        for (int s = 0; s < 2; ++s) {
            asm volatile("mbarrier.arrive.expect_tx.shared.b64 _, [%0], %1;"
                         :: "r"(mb[s]), "r"(CHUNK_BYTES) : "memory");
            asm volatile("cp.async.bulk.shared::cta.global.mbarrier::complete_tx::bytes "
                         "[%0], [%1], %2, [%3];"
                         :: "r"(sb[s]), "l"(src + (size_t)(bid + s * BPM) * CHUNK_BYTES),
                            "r"(CHUNK_BYTES), "r"(mb[s]) : "memory");
        }
    }

    float ax = 0.f, ay = 0.f, az = 0.f, aw = 0.f;
    int ph0 = 0, ph1 = 0;

    for (int i = 0; i < n_chunks; ++i) {
        const int s = i & 1;
        const uint32_t mbar = mb[s];
        const int phase = s ? ph1 : ph0;

        // wait for stage s (acquire: orders TMA writes before our smem reads)
        uint32_t done = 0;
        while (!done) {
            asm volatile(
                "{\n\t.reg .pred p;\n\t"
                "mbarrier.try_wait.parity.shared.b64 p, [%1], %2;\n\t"
                "selp.u32 %0, 1, 0, p;\n\t}"
                : "=r"(done) : "r"(mbar), "r"(phase) : "memory");
        }
        if (s) ph1 ^= 1; else ph0 ^= 1;

        // reduce: thread t owns float4-column t of every chunk (4 rows/chunk)
        const float4* buf = s_buf[s];
        float4 v0 = buf[t];
        float4 v1 = buf[t + 128];
        float4 v2 = buf[t + 256];
        float4 v3 = buf[t + 384];
        ax += (v0.x + v1.x) + (v2.x + v3.x);
        ay += (v0.y + v1.y) + (v2.y + v3.y);
        az += (v0.z + v1.z) + (v2.z + v3.z);
        aw += (v0.w + v1.w) + (v2.w + v3.w);

        __syncthreads();   // all threads done reading stage s

        // refill stage s with chunk i+2
        if (t == 0 && i + 2 < n_chunks) {
            asm volatile("mbarrier.arrive.expect_tx.shared.b64 _, [%0], %1;"
                         :: "r"(mbar), "r"(CHUNK_BYTES) : "memory");
            asm volatile("cp.async.bulk.shared::cta.global.mbarrier::complete_tx::bytes "
                         "[%0], [%1], %2, [%3];"
                         :: "r"(sb[s]), "l"(src + (size_t)(bid + (i + 2) * BPM) * CHUNK_BYTES),
                            "r"(CHUNK_BYTES), "r"(mbar) : "memory");
        }
    }

    // global accumulate: thread t owns columns 4t..4t+3
    float* dst = g_colsum + mat * 512 + t * 4;
    atomicAdd(dst + 0, ax);
    atomicAdd(dst + 1, ay);
    atomicAdd(dst + 2, az);
    atomicAdd(dst + 3, aw);
    __threadfence();

    __syncthreads();
    if (t == 0) s_rank = atomicAdd(&g_count, 1u);
    __syncthreads();

    // last-arriving block: fp64 dot, write out, reset scratch
    if (s_rank == GRID - 1) {
        __threadfence();
        double pr = 0.0;
        #pragma unroll
        for (int j = 0; j < 4; ++j) {
            int c = t + j * 128;
            pr += (double)__ldcg(&g_colsum[c]) * (double)__ldcg(&g_colsum[512 + c]);
        }
        #pragma unroll
        for (int o = 16; o > 0; o >>= 1)
            pr += __shfl_down_sync(0xffffffffu, pr, o);
        if ((t & 31) == 0) s_warp[t >> 5] = pr;
        __syncthreads();

        if (t == 0) {
            double v4 = s_warp[0] + s_warp[1] + s_warp[2] + s_warp[3];
            double loss = 2.0 * v4 / ((double)16384 * (double)16384);
            out[0] = (float)(loss < 1e-7 ? 1e-7 : loss);
        }
        __syncthreads();

        // reset for next graph replay
        #pragma unroll
        for (int j = 0; j < 8; ++j)
            g_colsum[t + j * 128] = 0.f;
        if (t == 0) g_count = 0u;
    }
}

extern "C" void kernel_launch(void* const* d_in, const int* in_sizes, int n_in,
                              void* d_out, int out_size) {
    const float* a = (const float*)d_in[0];
    const float* b = (const float*)d_in[1];
    float* out = (float*)d_out;

    qgc_tma<<<GRID, TPB>>>(a, b, out);
}